// round 3
// baseline (speedup 1.0000x reference)
#include <cuda_runtime.h>

#define Bsz 64
#define Tlen 128
#define Sn 100
#define An 16
#define Hd 120
#define G4 480      // 4*H
#define Kd 136      // A + H
#define Nrows 6400  // B*S
#define ROWS 32
#define NBLK 200    // 6400/32
#define LTHREADS 480
#define TAUF 5.0f
#define SMEM_LSTM (ROWS * (Kd + Hd + G4) * 4)

// ---------------- scratch (static device allocations only) ----------------
__device__ float g_Wt[Kd * G4];        // combined [x;h] weight, k-major
__device__ float g_bias[G4];           // b_ih + b_hh
__device__ float g_hfinal[Nrows * Hd];
__device__ float g_foo[Bsz * Sn * Sn];
__device__ float g_W2t[10000 * 256];   // W2 transposed (k-major)
__device__ float g_W3t[256 * Sn];      // W3 transposed (k-major)

// ---------------- prep: build fused/transposed weights --------------------
__global__ void prep_kernel(const float* __restrict__ W_ih,
                            const float* __restrict__ W_hh,
                            const float* __restrict__ b_ih,
                            const float* __restrict__ b_hh,
                            const float* __restrict__ W2,
                            const float* __restrict__ W3) {
    int idx = blockIdx.x * blockDim.x + threadIdx.x;
    if (idx < Kd * G4) {
        int k = idx / G4, j = idx - k * G4;
        g_Wt[idx] = (k < An) ? W_ih[j * An + k] : W_hh[j * Hd + (k - An)];
    }
    if (idx < G4) g_bias[idx] = b_ih[idx] + b_hh[idx];
    if (idx < 10000 * 256) {
        int k = idx >> 8, m = idx & 255;
        g_W2t[idx] = W2[m * 10000 + k];
    }
    if (idx < 256 * Sn) {
        int k = idx / Sn, j = idx - k * Sn;
        g_W3t[idx] = W3[j * 256 + k];
    }
}

// ---------------- LSTM: row-partitioned persistent-state kernel ------------
__device__ __forceinline__ float sigf(float v) {
    return 1.0f / (1.0f + __expf(-v));
}
__device__ __forceinline__ float tanhfast(float v) {
    return 2.0f / (1.0f + __expf(-2.0f * v)) - 1.0f;
}

__global__ void __launch_bounds__(LTHREADS, 1)
lstm_kernel(const float* __restrict__ x) {
    extern __shared__ float sm[];
    float* sh = sm;                    // [ROWS][Kd]  : [x_t | h]
    float* cc = sm + ROWS * Kd;        // [ROWS][Hd]  : cell state
    float* gg = cc + ROWS * Hd;        // [ROWS][G4]  : gate pre-activations

    const int tid = threadIdx.x;       // column j in [0, 480)
    const int row0 = blockIdx.x * ROWS;

    for (int i = tid; i < ROWS * Kd; i += LTHREADS) sh[i] = 0.0f;
    for (int i = tid; i < ROWS * Hd; i += LTHREADS) cc[i] = 0.0f;
    const float bj = g_bias[tid];

    // Each thread stages at most 2 (row, feature) pairs of x_t per step
    // (ROWS*An = 512 with 480 threads). Precompute their addresses.
    int st_r[2], st_a[2];
    long st_base[2];
    int n_st = 0;
    for (int i = tid; i < ROWS * An; i += LTHREADS) {
        int r = i >> 4, a = i & 15;
        int n = row0 + r;
        int b = n / Sn, s = n - b * Sn;
        st_r[n_st] = r; st_a[n_st] = a;
        st_base[n_st] = ((long)(b * Tlen) * Sn + s) * An + a;
        n_st++;
    }
    __syncthreads();

    for (int t = 0; t < Tlen; ++t) {
        for (int q = 0; q < n_st; ++q)
            sh[st_r[q] * Kd + st_a[q]] = x[st_base[q] + (long)t * (Sn * An)];
        __syncthreads();

        // GEMM: g[r][j] = bias[j] + sum_k sh[r][k] * Wt[k][j]
        float acc[ROWS];
#pragma unroll
        for (int r = 0; r < ROWS; ++r) acc[r] = bj;

        const float* wp = g_Wt + tid;
#pragma unroll 1
        for (int k = 0; k < Kd; k += 4) {
            const float w0 = wp[(k + 0) * G4];
            const float w1 = wp[(k + 1) * G4];
            const float w2 = wp[(k + 2) * G4];
            const float w3 = wp[(k + 3) * G4];
#pragma unroll
            for (int r = 0; r < ROWS; ++r) {
                const float4 v = *reinterpret_cast<const float4*>(&sh[r * Kd + k]);
                acc[r] = fmaf(v.x, w0, acc[r]);
                acc[r] = fmaf(v.y, w1, acc[r]);
                acc[r] = fmaf(v.z, w2, acc[r]);
                acc[r] = fmaf(v.w, w3, acc[r]);
            }
        }
#pragma unroll
        for (int r = 0; r < ROWS; ++r) gg[r * G4 + tid] = acc[r];
        __syncthreads();

        // gates + state update (PyTorch order i, f, g, o)
        for (int i = tid; i < ROWS * Hd; i += LTHREADS) {
            int r = i / Hd, u = i - r * Hd;
            const float* gr = gg + r * G4;
            float si = sigf(gr[u]);
            float sf = sigf(gr[Hd + u]);
            float tg = tanhfast(gr[2 * Hd + u]);
            float so = sigf(gr[3 * Hd + u]);
            float cn = fmaf(sf, cc[i], si * tg);
            cc[i] = cn;
            sh[r * Kd + An + u] = so * tanhfast(cn);
        }
        __syncthreads();
    }

    for (int i = tid; i < ROWS * Hd; i += LTHREADS) {
        int r = i / Hd, u = i - r * Hd;
        g_hfinal[(row0 + r) * Hd + u] = sh[r * Kd + An + u];
    }
}

// ---------------- score + NeuralSort (one block per batch) -----------------
__global__ void __launch_bounds__(128)
sort_kernel(const float* __restrict__ w_lin, const float* __restrict__ b_lin) {
    __shared__ float s[Sn];
    __shared__ float rs[Sn];
    __shared__ float wl[Hd];
    const int b = blockIdx.x, tid = threadIdx.x;

    if (tid < Hd) wl[tid] = w_lin[tid];
    __syncthreads();

    if (tid < Sn) {
        const float* hp = g_hfinal + (b * Sn + tid) * Hd;
        float a = b_lin[0];
        for (int k = 0; k < Hd; ++k) a = fmaf(hp[k], wl[k], a);
        s[tid] = a;
    }
    __syncthreads();

    if (tid < Sn) {
        float sj = s[tid], a = 0.0f;
        for (int i = 0; i < Sn; ++i) a += fabsf(sj - s[i]);
        rs[tid] = a;
    }
    __syncthreads();

    const int wid = tid >> 5, lane = tid & 31;
    for (int i = wid; i < Sn; i += 4) {
        const float scale = (float)(Sn - 1 - 2 * i);
        float v[4];
        float mx = -1e30f;
#pragma unroll
        for (int q = 0; q < 4; ++q) {
            int j = lane + q * 32;
            v[q] = (j < Sn) ? (s[j] * scale - rs[j]) * (1.0f / TAUF) : -1e30f;
            mx = fmaxf(mx, v[q]);
        }
#pragma unroll
        for (int o = 16; o; o >>= 1) mx = fmaxf(mx, __shfl_xor_sync(0xffffffffu, mx, o));
        float e[4];
        float sum = 0.0f;
#pragma unroll
        for (int q = 0; q < 4; ++q) {
            int j = lane + q * 32;
            e[q] = (j < Sn) ? __expf(v[q] - mx) : 0.0f;
            sum += e[q];
        }
#pragma unroll
        for (int o = 16; o; o >>= 1) sum += __shfl_xor_sync(0xffffffffu, sum, o);
        const float inv = 1.0f / sum;
#pragma unroll
        for (int q = 0; q < 4; ++q) {
            int j = lane + q * 32;
            if (j < Sn) g_foo[(b * Sn + i) * Sn + j] = e[q] * inv;
        }
    }
}

// ---------------- MLP + final softmax (one block per batch) ----------------
__global__ void __launch_bounds__(256)
mlp_kernel(const float* __restrict__ b2, const float* __restrict__ b3,
           float* __restrict__ out) {
    __shared__ float sfoo[10000];
    __shared__ float z1[256];
    __shared__ float z2[Sn];
    const int b = blockIdx.x, tid = threadIdx.x;

    const float* fp = g_foo + b * 10000;
    for (int i = tid; i < 10000; i += 256) sfoo[i] = fp[i];
    __syncthreads();

    float a = b2[tid];
    const float* w = g_W2t + tid;
#pragma unroll 4
    for (int k = 0; k < 10000; ++k) a = fmaf(sfoo[k], w[k * 256], a);
    z1[tid] = fmaxf(a, 0.0f);
    __syncthreads();

    if (tid < Sn) {
        float a2 = b3[tid];
        const float* w3 = g_W3t + tid;
#pragma unroll 4
        for (int k = 0; k < 256; ++k) a2 = fmaf(z1[k], w3[k * Sn], a2);
        z2[tid] = a2;
    }
    __syncthreads();

    if (tid < Sn) {
        float mx = -1e30f;
        for (int i = 0; i < Sn; ++i) mx = fmaxf(mx, z2[i]);
        float sum = 0.0f;
        for (int i = 0; i < Sn; ++i) sum += __expf(z2[i] - mx);
        out[b * Sn + tid] = __expf(z2[tid] - mx) / sum;
    }
}

// ---------------- launch ---------------------------------------------------
extern "C" void kernel_launch(void* const* d_in, const int* in_sizes, int n_in,
                              void* d_out, int out_size) {
    const float* x     = (const float*)d_in[0];
    const float* W_ih  = (const float*)d_in[1];
    const float* W_hh  = (const float*)d_in[2];
    const float* b_ih  = (const float*)d_in[3];
    const float* b_hh  = (const float*)d_in[4];
    const float* w_lin = (const float*)d_in[5];
    const float* b_lin = (const float*)d_in[6];
    const float* W2    = (const float*)d_in[7];
    const float* b2    = (const float*)d_in[8];
    const float* W3    = (const float*)d_in[9];
    const float* b3    = (const float*)d_in[10];
    float* out = (float*)d_out;

    static int smem_set = 0;
    if (!smem_set) {
        cudaFuncSetAttribute(lstm_kernel,
                             cudaFuncAttributeMaxDynamicSharedMemorySize,
                             SMEM_LSTM);
        smem_set = 1;
    }

    prep_kernel<<<10000, 256>>>(W_ih, W_hh, b_ih, b_hh, W2, W3);
    lstm_kernel<<<NBLK, LTHREADS, SMEM_LSTM>>>(x);
    sort_kernel<<<Bsz, 128>>>(w_lin, b_lin);
    mlp_kernel<<<Bsz, 256>>>(b2, b3, out);
}

// round 4
// speedup vs baseline: 1.6864x; 1.6864x over previous
#include <cuda_runtime.h>

#define Bsz 64
#define Tlen 128
#define Sn 100
#define An 16
#define Hd 120
#define G4 480      // 4*H
#define Kd 136      // A + H
#define Nrows 6400  // B*S
#define ROWS 44
#define NPAIR 22    // ROWS/2
#define PK (Kd * 2) // floats per row-pair slab (interleaved)
#define NBLK 146    // ceil(6400/44)
#define LTHREADS 480
#define TAUF 5.0f
#define SMEM_LSTM ((NPAIR * PK + ROWS * Hd + ROWS * G4) * 4)

// ---------------- scratch (static device allocations only) ----------------
__device__ float g_Wt[Kd * G4];        // combined [x;h] weight, k-major
__device__ float g_bias[G4];           // b_ih + b_hh
__device__ float g_hfinal[Nrows * Hd];
__device__ float g_foo[Bsz * Sn * Sn];
__device__ float g_W2t[10000 * 256];   // W2 transposed (k-major)
__device__ float g_W3t[256 * Sn];      // W3 transposed (k-major)

// ---------------- packed f32x2 helpers -------------------------------------
__device__ __forceinline__ unsigned long long ffma2(unsigned long long a,
                                                    unsigned long long b,
                                                    unsigned long long c) {
    unsigned long long d;
    asm("fma.rn.f32x2 %0, %1, %2, %3;" : "=l"(d) : "l"(a), "l"(b), "l"(c));
    return d;
}
__device__ __forceinline__ unsigned long long pack2(float v) {
    unsigned long long r;
    asm("mov.b64 %0, {%1, %1};" : "=l"(r) : "f"(v));
    return r;
}
__device__ __forceinline__ float lo32(unsigned long long a) {
    return __uint_as_float((unsigned)(a & 0xffffffffULL));
}
__device__ __forceinline__ float hi32(unsigned long long a) {
    return __uint_as_float((unsigned)(a >> 32));
}

// ---------------- prep: build fused/transposed weights --------------------
__global__ void prep_kernel(const float* __restrict__ W_ih,
                            const float* __restrict__ W_hh,
                            const float* __restrict__ b_ih,
                            const float* __restrict__ b_hh,
                            const float* __restrict__ W2,
                            const float* __restrict__ W3) {
    int idx = blockIdx.x * blockDim.x + threadIdx.x;
    if (idx < Kd * G4) {
        int k = idx / G4, j = idx - k * G4;
        g_Wt[idx] = (k < An) ? W_ih[j * An + k] : W_hh[j * Hd + (k - An)];
    }
    if (idx < G4) g_bias[idx] = b_ih[idx] + b_hh[idx];
    if (idx < 10000 * 256) {
        int k = idx >> 8, m = idx & 255;
        g_W2t[idx] = W2[m * 10000 + k];
    }
    if (idx < 256 * Sn) {
        int k = idx / Sn, j = idx - k * Sn;
        g_W3t[idx] = W3[j * 256 + k];
    }
}

// ---------------- gate nonlinearities --------------------------------------
__device__ __forceinline__ float sigf(float v) {
    return __fdividef(1.0f, 1.0f + __expf(-v));
}
__device__ __forceinline__ float tanhfast(float v) {
    return __fdividef(2.0f, 1.0f + __expf(-2.0f * v)) - 1.0f;
}

// ---------------- LSTM: row-partitioned persistent-state kernel ------------
// Shared layout: sh2 interleaves row pairs: element (r,k) lives at
//   sh2[(r>>1)*PK + k*2 + (r&1)]
// so one 16B LDS yields (r0 k, r1 k, r0 k+1, r1 k+1) = two f32x2 operands.
__global__ void __launch_bounds__(LTHREADS, 1)
lstm_kernel(const float* __restrict__ x) {
    extern __shared__ float sm[];
    float* sh2 = sm;                    // [NPAIR][Kd][2] : [x_t | h]
    float* cc  = sm + NPAIR * PK;       // [ROWS][Hd]     : cell state
    float* gg  = cc + ROWS * Hd;        // [ROWS][G4]     : gate pre-act

    const int tid = threadIdx.x;        // output column j in [0, 480)
    const int row0 = blockIdx.x * ROWS;

    for (int i = tid; i < NPAIR * PK; i += LTHREADS) sh2[i] = 0.0f;
    for (int i = tid; i < ROWS * Hd; i += LTHREADS) cc[i] = 0.0f;
    const float bj = g_bias[tid];
    const unsigned long long bj2 = pack2(bj);

    // precompute x-staging slots: ROWS*An = 704, <=2 per thread
    int st_dst[2];
    long st_src[2];
    int n_st = 0;
    for (int i = tid; i < ROWS * An; i += LTHREADS) {
        int r = i >> 4, a = i & 15;
        int n = row0 + r;
        if (n < Nrows) {
            int b = n / Sn, s = n - b * Sn;
            st_dst[n_st] = (r >> 1) * PK + a * 2 + (r & 1);
            st_src[n_st] = ((long)(b * Tlen) * Sn + s) * An + a;
            n_st++;
        }
    }

    // gate-phase fixed decomposition: tid = r0*Hd + u  (stride 480 = 4*Hd)
    const int g_r0 = tid / Hd;          // 0..3
    const int g_u  = tid - g_r0 * Hd;   // 0..119

    __syncthreads();
    // stage x_0
    for (int q = 0; q < n_st; ++q) sh2[st_dst[q]] = x[st_src[q]];
    __syncthreads();

    for (int t = 0; t < Tlen; ++t) {
        // ---- GEMM: g[r][j] = bias[j] + sum_k act[r][k] * Wt[k][j] ----
        unsigned long long acc[NPAIR];
#pragma unroll
        for (int p = 0; p < NPAIR; ++p) acc[p] = bj2;

        const float* wp = g_Wt + tid;
        float w0 = wp[0], w1 = wp[G4];
#pragma unroll 2
        for (int k = 0; k < Kd; k += 2) {
            // prefetch next k-pair's weights (clamped to stay in-bounds)
            const int kn = (k + 2 < Kd) ? (k + 2) : 0;
            const float nw0 = wp[kn * G4];
            const float nw1 = wp[(kn + 1) * G4];
            const unsigned long long w0x2 = pack2(w0);
            const unsigned long long w1x2 = pack2(w1);
            const float* skp = sh2 + k * 2;
#pragma unroll
            for (int p = 0; p < NPAIR; ++p) {
                const ulonglong2 v =
                    *reinterpret_cast<const ulonglong2*>(skp + p * PK);
                acc[p] = ffma2(v.x, w0x2, acc[p]);
                acc[p] = ffma2(v.y, w1x2, acc[p]);
            }
            w0 = nw0; w1 = nw1;
        }
#pragma unroll
        for (int p = 0; p < NPAIR; ++p) {
            gg[(2 * p) * G4 + tid]     = lo32(acc[p]);
            gg[(2 * p + 1) * G4 + tid] = hi32(acc[p]);
        }
        __syncthreads();

        // ---- gates + state update (i, f, g, o) + stage x_{t+1} ----
#pragma unroll
        for (int q = 0; q < 11; ++q) {
            const int r = g_r0 + 4 * q;     // 0..43
            const float* gr = gg + r * G4;
            const float si = sigf(gr[g_u]);
            const float sf = sigf(gr[Hd + g_u]);
            const float tg = tanhfast(gr[2 * Hd + g_u]);
            const float so = sigf(gr[3 * Hd + g_u]);
            const int ci = r * Hd + g_u;
            const float cn = fmaf(sf, cc[ci], si * tg);
            cc[ci] = cn;
            sh2[(r >> 1) * PK + (An + g_u) * 2 + (r & 1)] = so * tanhfast(cn);
        }
        if (t + 1 < Tlen) {
            const long toff = (long)(t + 1) * (Sn * An);
            for (int q = 0; q < n_st; ++q)
                sh2[st_dst[q]] = x[st_src[q] + toff];
        }
        __syncthreads();
    }

    for (int q = 0; q < 11; ++q) {
        const int r = g_r0 + 4 * q;
        const int n = row0 + r;
        if (n < Nrows)
            g_hfinal[n * Hd + g_u] =
                sh2[(r >> 1) * PK + (An + g_u) * 2 + (r & 1)];
    }
}

// ---------------- score + NeuralSort (one block per batch) -----------------
__global__ void __launch_bounds__(128)
sort_kernel(const float* __restrict__ w_lin, const float* __restrict__ b_lin) {
    __shared__ float s[Sn];
    __shared__ float rs[Sn];
    __shared__ float wl[Hd];
    const int b = blockIdx.x, tid = threadIdx.x;

    if (tid < Hd) wl[tid] = w_lin[tid];
    __syncthreads();

    if (tid < Sn) {
        const float* hp = g_hfinal + (b * Sn + tid) * Hd;
        float a = b_lin[0];
        for (int k = 0; k < Hd; ++k) a = fmaf(hp[k], wl[k], a);
        s[tid] = a;
    }
    __syncthreads();

    if (tid < Sn) {
        float sj = s[tid], a = 0.0f;
        for (int i = 0; i < Sn; ++i) a += fabsf(sj - s[i]);
        rs[tid] = a;
    }
    __syncthreads();

    const int wid = tid >> 5, lane = tid & 31;
    for (int i = wid; i < Sn; i += 4) {
        const float scale = (float)(Sn - 1 - 2 * i);
        float v[4];
        float mx = -1e30f;
#pragma unroll
        for (int q = 0; q < 4; ++q) {
            int j = lane + q * 32;
            v[q] = (j < Sn) ? (s[j] * scale - rs[j]) * (1.0f / TAUF) : -1e30f;
            mx = fmaxf(mx, v[q]);
        }
#pragma unroll
        for (int o = 16; o; o >>= 1) mx = fmaxf(mx, __shfl_xor_sync(0xffffffffu, mx, o));
        float e[4];
        float sum = 0.0f;
#pragma unroll
        for (int q = 0; q < 4; ++q) {
            int j = lane + q * 32;
            e[q] = (j < Sn) ? __expf(v[q] - mx) : 0.0f;
            sum += e[q];
        }
#pragma unroll
        for (int o = 16; o; o >>= 1) sum += __shfl_xor_sync(0xffffffffu, sum, o);
        const float inv = __fdividef(1.0f, sum);
#pragma unroll
        for (int q = 0; q < 4; ++q) {
            int j = lane + q * 32;
            if (j < Sn) g_foo[(b * Sn + i) * Sn + j] = e[q] * inv;
        }
    }
}

// ---------------- MLP + final softmax (one block per batch) ----------------
__global__ void __launch_bounds__(256)
mlp_kernel(const float* __restrict__ b2, const float* __restrict__ b3,
           float* __restrict__ out) {
    __shared__ float sfoo[10000];
    __shared__ float z1[256];
    __shared__ float z2[Sn];
    const int b = blockIdx.x, tid = threadIdx.x;

    const float* fp = g_foo + b * 10000;
    for (int i = tid; i < 10000; i += 256) sfoo[i] = fp[i];
    __syncthreads();

    float a = b2[tid];
    const float* w = g_W2t + tid;
#pragma unroll 4
    for (int k = 0; k < 10000; ++k) a = fmaf(sfoo[k], w[k * 256], a);
    z1[tid] = fmaxf(a, 0.0f);
    __syncthreads();

    if (tid < Sn) {
        float a2 = b3[tid];
        const float* w3 = g_W3t + tid;
#pragma unroll 4
        for (int k = 0; k < 256; ++k) a2 = fmaf(z1[k], w3[k * Sn], a2);
        z2[tid] = a2;
    }
    __syncthreads();

    if (tid < Sn) {
        float mx = -1e30f;
        for (int i = 0; i < Sn; ++i) mx = fmaxf(mx, z2[i]);
        float sum = 0.0f;
        for (int i = 0; i < Sn; ++i) sum += __expf(z2[i] - mx);
        out[b * Sn + tid] = __expf(z2[tid] - mx) * __fdividef(1.0f, sum);
    }
}

// ---------------- launch ---------------------------------------------------
extern "C" void kernel_launch(void* const* d_in, const int* in_sizes, int n_in,
                              void* d_out, int out_size) {
    const float* x     = (const float*)d_in[0];
    const float* W_ih  = (const float*)d_in[1];
    const float* W_hh  = (const float*)d_in[2];
    const float* b_ih  = (const float*)d_in[3];
    const float* b_hh  = (const float*)d_in[4];
    const float* w_lin = (const float*)d_in[5];
    const float* b_lin = (const float*)d_in[6];
    const float* W2    = (const float*)d_in[7];
    const float* b2    = (const float*)d_in[8];
    const float* W3    = (const float*)d_in[9];
    const float* b3    = (const float*)d_in[10];
    float* out = (float*)d_out;

    static int smem_set = 0;
    if (!smem_set) {
        cudaFuncSetAttribute(lstm_kernel,
                             cudaFuncAttributeMaxDynamicSharedMemorySize,
                             SMEM_LSTM);
        smem_set = 1;
    }

    prep_kernel<<<10000, 256>>>(W_ih, W_hh, b_ih, b_hh, W2, W3);
    lstm_kernel<<<NBLK, LTHREADS, SMEM_LSTM>>>(x);
    sort_kernel<<<Bsz, 128>>>(w_lin, b_lin);
    mlp_kernel<<<Bsz, 256>>>(b2, b3, out);
}

// round 6
// speedup vs baseline: 1.6882x; 1.0011x over previous
#include <cuda_runtime.h>

#define Bsz 64
#define Tlen 128
#define Sn 100
#define An 16
#define Hd 120
#define G4 480      // 4*H
#define Kd 136      // A + H
#define Nrows 6400  // B*S
#define ROWS 44
#define NPAIR 22    // ROWS/2
#define PK (Kd * 2) // floats per row-pair slab (interleaved)
#define NBLK 146    // ceil(6400/44)
#define LTHREADS 480
#define TAUF 5.0f
#define SMEM_LSTM ((NPAIR * PK + ROWS * Hd + ROWS * G4) * 4)

// ---------------- scratch (static device allocations only) ----------------
__device__ float g_Wt[Kd * G4];        // combined [x;h] weight, k-major
__device__ float g_bias[G4];           // b_ih + b_hh
__device__ float g_hfinal[Nrows * Hd];
__device__ float g_foo[Bsz * Sn * Sn];
__device__ float g_W2t[10000 * 256];   // W2 transposed (k-major)
__device__ float g_W3t[256 * Sn];      // W3 transposed (k-major)

// ---------------- packed f32x2 helpers -------------------------------------
__device__ __forceinline__ unsigned long long ffma2(unsigned long long a,
                                                    unsigned long long b,
                                                    unsigned long long c) {
    unsigned long long d;
    asm("fma.rn.f32x2 %0, %1, %2, %3;" : "=l"(d) : "l"(a), "l"(b), "l"(c));
    return d;
}
__device__ __forceinline__ unsigned long long pack2(float v) {
    unsigned long long r;
    asm("mov.b64 %0, {%1, %1};" : "=l"(r) : "f"(v));
    return r;
}
__device__ __forceinline__ float lo32(unsigned long long a) {
    return __uint_as_float((unsigned)(a & 0xffffffffULL));
}
__device__ __forceinline__ float hi32(unsigned long long a) {
    return __uint_as_float((unsigned)(a >> 32));
}

// ---------------- prep: build fused/transposed weights --------------------
__global__ void prep_kernel(const float* __restrict__ W_ih,
                            const float* __restrict__ W_hh,
                            const float* __restrict__ b_ih,
                            const float* __restrict__ b_hh,
                            const float* __restrict__ W2,
                            const float* __restrict__ W3) {
    int idx = blockIdx.x * blockDim.x + threadIdx.x;
    if (idx < Kd * G4) {
        int k = idx / G4, j = idx - k * G4;
        g_Wt[idx] = (k < An) ? W_ih[j * An + k] : W_hh[j * Hd + (k - An)];
    }
    if (idx < G4) g_bias[idx] = b_ih[idx] + b_hh[idx];
    if (idx < 10000 * 256) {
        int k = idx >> 8, m = idx & 255;
        g_W2t[idx] = W2[m * 10000 + k];
    }
    if (idx < 256 * Sn) {
        int k = idx / Sn, j = idx - k * Sn;
        g_W3t[idx] = W3[j * 256 + k];
    }
}

// ---------------- gate nonlinearities --------------------------------------
__device__ __forceinline__ float sigf(float v) {
    return __fdividef(1.0f, 1.0f + __expf(-v));
}
__device__ __forceinline__ float tanhfast(float v) {
    return __fdividef(2.0f, 1.0f + __expf(-2.0f * v)) - 1.0f;
}

// ---------------- LSTM: row-partitioned persistent-state kernel ------------
// Shared layout: sh2 interleaves row pairs: element (r,k) lives at
//   sh2[(r>>1)*PK + k*2 + (r&1)]
// so one 16B LDS yields (r0 k, r1 k, r0 k+1, r1 k+1) = two f32x2 operands.
__global__ void __launch_bounds__(LTHREADS, 1)
lstm_kernel(const float* __restrict__ x) {
    extern __shared__ float sm[];
    float* sh2 = sm;                    // [NPAIR][Kd][2] : [x_t | h]
    float* cc  = sm + NPAIR * PK;       // [ROWS][Hd]     : cell state
    float* gg  = cc + ROWS * Hd;        // [ROWS][G4]     : gate pre-act

    const int tid = threadIdx.x;        // output column j in [0, 480)
    const int row0 = blockIdx.x * ROWS;

    for (int i = tid; i < NPAIR * PK; i += LTHREADS) sh2[i] = 0.0f;
    for (int i = tid; i < ROWS * Hd; i += LTHREADS) cc[i] = 0.0f;
    const float bj = g_bias[tid];
    const unsigned long long bj2 = pack2(bj);

    // precompute x-staging slots: ROWS*An = 704, <=2 per thread
    int st_dst[2];
    long st_src[2];
    int n_st = 0;
    for (int i = tid; i < ROWS * An; i += LTHREADS) {
        int r = i >> 4, a = i & 15;
        int n = row0 + r;
        if (n < Nrows) {
            int b = n / Sn, s = n - b * Sn;
            st_dst[n_st] = (r >> 1) * PK + a * 2 + (r & 1);
            st_src[n_st] = ((long)(b * Tlen) * Sn + s) * An + a;
            n_st++;
        }
    }

    // gate-phase fixed decomposition: tid = r0*Hd + u  (stride 480 = 4*Hd)
    const int g_r0 = tid / Hd;          // 0..3
    const int g_u  = tid - g_r0 * Hd;   // 0..119

    __syncthreads();
    // stage x_0
    for (int q = 0; q < n_st; ++q) sh2[st_dst[q]] = x[st_src[q]];
    __syncthreads();

    for (int t = 0; t < Tlen; ++t) {
        // ---- GEMM: g[r][j] = bias[j] + sum_k act[r][k] * Wt[k][j] ----
        unsigned long long acc[NPAIR];
#pragma unroll
        for (int p = 0; p < NPAIR; ++p) acc[p] = bj2;

        const float* wp = g_Wt + tid;
        float w0 = wp[0], w1 = wp[G4];
#pragma unroll 2
        for (int k = 0; k < Kd; k += 2) {
            // prefetch next k-pair's weights (clamped to stay in-bounds)
            const int kn = (k + 2 < Kd) ? (k + 2) : 0;
            const float nw0 = wp[kn * G4];
            const float nw1 = wp[(kn + 1) * G4];
            const unsigned long long w0x2 = pack2(w0);
            const unsigned long long w1x2 = pack2(w1);
            const float* skp = sh2 + k * 2;
#pragma unroll
            for (int p = 0; p < NPAIR; ++p) {
                const ulonglong2 v =
                    *reinterpret_cast<const ulonglong2*>(skp + p * PK);
                acc[p] = ffma2(v.x, w0x2, acc[p]);
                acc[p] = ffma2(v.y, w1x2, acc[p]);
            }
            w0 = nw0; w1 = nw1;
        }
#pragma unroll
        for (int p = 0; p < NPAIR; ++p) {
            gg[(2 * p) * G4 + tid]     = lo32(acc[p]);
            gg[(2 * p + 1) * G4 + tid] = hi32(acc[p]);
        }
        __syncthreads();

        // ---- gates + state update (i, f, g, o) + stage x_{t+1} ----
#pragma unroll
        for (int q = 0; q < 11; ++q) {
            const int r = g_r0 + 4 * q;     // 0..43
            const float* gr = gg + r * G4;
            const float si = sigf(gr[g_u]);
            const float sf = sigf(gr[Hd + g_u]);
            const float tg = tanhfast(gr[2 * Hd + g_u]);
            const float so = sigf(gr[3 * Hd + g_u]);
            const int ci = r * Hd + g_u;
            const float cn = fmaf(sf, cc[ci], si * tg);
            cc[ci] = cn;
            sh2[(r >> 1) * PK + (An + g_u) * 2 + (r & 1)] = so * tanhfast(cn);
        }
        if (t + 1 < Tlen) {
            const long toff = (long)(t + 1) * (Sn * An);
            for (int q = 0; q < n_st; ++q)
                sh2[st_dst[q]] = x[st_src[q] + toff];
        }
        __syncthreads();
    }

    for (int q = 0; q < 11; ++q) {
        const int r = g_r0 + 4 * q;
        const int n = row0 + r;
        if (n < Nrows)
            g_hfinal[n * Hd + g_u] =
                sh2[(r >> 1) * PK + (An + g_u) * 2 + (r & 1)];
    }
}

// ---------------- score + NeuralSort (one block per batch) -----------------
__global__ void __launch_bounds__(128)
sort_kernel(const float* __restrict__ w_lin, const float* __restrict__ b_lin) {
    __shared__ float s[Sn];
    __shared__ float rs[Sn];
    __shared__ float wl[Hd];
    const int b = blockIdx.x, tid = threadIdx.x;

    if (tid < Hd) wl[tid] = w_lin[tid];
    __syncthreads();

    if (tid < Sn) {
        const float* hp = g_hfinal + (b * Sn + tid) * Hd;
        float a = b_lin[0];
        for (int k = 0; k < Hd; ++k) a = fmaf(hp[k], wl[k], a);
        s[tid] = a;
    }
    __syncthreads();

    if (tid < Sn) {
        float sj = s[tid], a = 0.0f;
        for (int i = 0; i < Sn; ++i) a += fabsf(sj - s[i]);
        rs[tid] = a;
    }
    __syncthreads();

    const int wid = tid >> 5, lane = tid & 31;
    for (int i = wid; i < Sn; i += 4) {
        const float scale = (float)(Sn - 1 - 2 * i);
        float v[4];
        float mx = -1e30f;
#pragma unroll
        for (int q = 0; q < 4; ++q) {
            int j = lane + q * 32;
            v[q] = (j < Sn) ? (s[j] * scale - rs[j]) * (1.0f / TAUF) : -1e30f;
            mx = fmaxf(mx, v[q]);
        }
#pragma unroll
        for (int o = 16; o; o >>= 1) mx = fmaxf(mx, __shfl_xor_sync(0xffffffffu, mx, o));
        float e[4];
        float sum = 0.0f;
#pragma unroll
        for (int q = 0; q < 4; ++q) {
            int j = lane + q * 32;
            e[q] = (j < Sn) ? __expf(v[q] - mx) : 0.0f;
            sum += e[q];
        }
#pragma unroll
        for (int o = 16; o; o >>= 1) sum += __shfl_xor_sync(0xffffffffu, sum, o);
        const float inv = __fdividef(1.0f, sum);
#pragma unroll
        for (int q = 0; q < 4; ++q) {
            int j = lane + q * 32;
            if (j < Sn) g_foo[(b * Sn + i) * Sn + j] = e[q] * inv;
        }
    }
}

// ---------------- MLP + final softmax (one block per batch) ----------------
__global__ void __launch_bounds__(256)
mlp_kernel(const float* __restrict__ b2, const float* __restrict__ b3,
           float* __restrict__ out) {
    __shared__ float sfoo[10000];
    __shared__ float z1[256];
    __shared__ float z2[Sn];
    const int b = blockIdx.x, tid = threadIdx.x;

    const float* fp = g_foo + b * 10000;
    for (int i = tid; i < 10000; i += 256) sfoo[i] = fp[i];
    __syncthreads();

    float a = b2[tid];
    const float* w = g_W2t + tid;
#pragma unroll 4
    for (int k = 0; k < 10000; ++k) a = fmaf(sfoo[k], w[k * 256], a);
    z1[tid] = fmaxf(a, 0.0f);
    __syncthreads();

    if (tid < Sn) {
        float a2 = b3[tid];
        const float* w3 = g_W3t + tid;
#pragma unroll 4
        for (int k = 0; k < 256; ++k) a2 = fmaf(z1[k], w3[k * Sn], a2);
        z2[tid] = a2;
    }
    __syncthreads();

    if (tid < Sn) {
        float mx = -1e30f;
        for (int i = 0; i < Sn; ++i) mx = fmaxf(mx, z2[i]);
        float sum = 0.0f;
        for (int i = 0; i < Sn; ++i) sum += __expf(z2[i] - mx);
        out[b * Sn + tid] = __expf(z2[tid] - mx) * __fdividef(1.0f, sum);
    }
}

// ---------------- launch ---------------------------------------------------
extern "C" void kernel_launch(void* const* d_in, const int* in_sizes, int n_in,
                              void* d_out, int out_size) {
    const float* x     = (const float*)d_in[0];
    const float* W_ih  = (const float*)d_in[1];
    const float* W_hh  = (const float*)d_in[2];
    const float* b_ih  = (const float*)d_in[3];
    const float* b_hh  = (const float*)d_in[4];
    const float* w_lin = (const float*)d_in[5];
    const float* b_lin = (const float*)d_in[6];
    const float* W2    = (const float*)d_in[7];
    const float* b2    = (const float*)d_in[8];
    const float* W3    = (const float*)d_in[9];
    const float* b3    = (const float*)d_in[10];
    float* out = (float*)d_out;

    static int smem_set = 0;
    if (!smem_set) {
        cudaFuncSetAttribute(lstm_kernel,
                             cudaFuncAttributeMaxDynamicSharedMemorySize,
                             SMEM_LSTM);
        smem_set = 1;
    }

    prep_kernel<<<10000, 256>>>(W_ih, W_hh, b_ih, b_hh, W2, W3);
    lstm_kernel<<<NBLK, LTHREADS, SMEM_LSTM>>>(x);
    sort_kernel<<<Bsz, 128>>>(w_lin, b_lin);
    mlp_kernel<<<Bsz, 256>>>(b2, b3, out);
}